// round 3
// baseline (speedup 1.0000x reference)
#include <cuda_runtime.h>
#include <math.h>

#define BB 4
#define SS 2048
#define HID 1024
#define DD 64
#define RR (BB*SS)   // 8192 rows total
#define PAD 68       // smem row stride (floats): bank = 4*row+col -> conflict-free frag loads
#define VPAD 72      // k-major V tile: bank = 8*k+n -> conflict-free

// ---- scratch (static device arrays; no allocation) ----
static __device__ float g_q[RR*DD];
static __device__ float g_k[RR*DD];
static __device__ float g_v[RR*DD];
static __device__ float g_head[RR*DD];
static __device__ float g_scores[(size_t)RR*SS];   // 67 MB
static __device__ float g_weff[DD*HID];

// ---------------------------------------------------------------------------
// helpers: tf32 convert + mma.sync m16n8k8 tf32
// ---------------------------------------------------------------------------
__device__ __forceinline__ unsigned f2tf(float x) {
    unsigned r;
    asm("cvt.rna.tf32.f32 %0, %1;" : "=r"(r) : "f"(x));
    return r;
}
__device__ __forceinline__ void mma_tf32(float* c, const unsigned* a, const unsigned* b) {
    asm volatile(
        "mma.sync.aligned.m16n8k8.row.col.f32.tf32.tf32.f32 "
        "{%0,%1,%2,%3}, {%4,%5,%6,%7}, {%8,%9}, {%0,%1,%2,%3};"
        : "+f"(c[0]), "+f"(c[1]), "+f"(c[2]), "+f"(c[3])
        : "r"(a[0]), "r"(a[1]), "r"(a[2]), "r"(a[3]), "r"(b[0]), "r"(b[1]));
}

// ---------------------------------------------------------------------------
// K0: W_eff[r][c] = sum_{h=0}^{15} Wout[h*64+r][c]
// ---------------------------------------------------------------------------
__global__ void weff_kernel(const float* __restrict__ Wout) {
    int idx = blockIdx.x * 256 + threadIdx.x;   // < 64*1024
    int r = idx >> 10, c = idx & 1023;
    float s = 0.f;
#pragma unroll
    for (int h = 0; h < 16; h++) s += Wout[(size_t)(h*64 + r)*HID + c];
    g_weff[idx] = s;
}

// ---------------------------------------------------------------------------
// K1: Q/K/V projections: [8192,1024]@[1024,64]+b  (blockIdx.y selects q/k/v)
// ---------------------------------------------------------------------------
__global__ void __launch_bounds__(256) proj_kernel(
    const float* __restrict__ xq, const float* __restrict__ xk, const float* __restrict__ xv,
    const float* __restrict__ Wq, const float* __restrict__ Wk, const float* __restrict__ Wv,
    const float* __restrict__ bq, const float* __restrict__ bk, const float* __restrict__ bv)
{
    const int which = blockIdx.y;
    const float* X    = which == 0 ? xq : which == 1 ? xk : xv;
    const float* W    = which == 0 ? Wq : which == 1 ? Wk : Wv;
    const float* bias = which == 0 ? bq : which == 1 ? bk : bv;
    float*       O    = which == 0 ? g_q : which == 1 ? g_k : g_v;

    const int mbase = blockIdx.x * 64;
    __shared__ float Xs[16][65];                 // k-major: Xs[k][m]
    __shared__ __align__(16) float Ws[16][64];   // Ws[k][n]
    const int tid = threadIdx.x;
    const int tx = tid & 15, ty = tid >> 4;
    float acc[4][4] = {};

    for (int kk = 0; kk < HID; kk += 16) {
        {   // X tile 64x16 (transpose to k-major)
            int m  = tid >> 2;
            int k4 = (tid & 3) * 4;
            float4 v = *(const float4*)(X + (size_t)(mbase + m)*HID + kk + k4);
            Xs[k4+0][m] = v.x; Xs[k4+1][m] = v.y; Xs[k4+2][m] = v.z; Xs[k4+3][m] = v.w;
        }
        {   // W tile 16x64
            int k  = tid >> 4;
            int n4 = (tid & 15) * 4;
            *(float4*)&Ws[k][n4] = *(const float4*)(W + (size_t)(kk + k)*DD + n4);
        }
        __syncthreads();
#pragma unroll
        for (int k = 0; k < 16; k++) {
            float a0 = Xs[k][ty*4+0], a1 = Xs[k][ty*4+1];
            float a2 = Xs[k][ty*4+2], a3 = Xs[k][ty*4+3];
            float4 w = *(const float4*)&Ws[k][tx*4];
            acc[0][0] += a0*w.x; acc[0][1] += a0*w.y; acc[0][2] += a0*w.z; acc[0][3] += a0*w.w;
            acc[1][0] += a1*w.x; acc[1][1] += a1*w.y; acc[1][2] += a1*w.z; acc[1][3] += a1*w.w;
            acc[2][0] += a2*w.x; acc[2][1] += a2*w.y; acc[2][2] += a2*w.z; acc[2][3] += a2*w.w;
            acc[3][0] += a3*w.x; acc[3][1] += a3*w.y; acc[3][2] += a3*w.z; acc[3][3] += a3*w.w;
        }
        __syncthreads();
    }
    float4 bb = *(const float4*)(bias + tx*4);
#pragma unroll
    for (int i = 0; i < 4; i++) {
        float4 o = make_float4(acc[i][0]+bb.x, acc[i][1]+bb.y, acc[i][2]+bb.z, acc[i][3]+bb.w);
        *(float4*)(O + (size_t)(mbase + ty*4 + i)*DD + tx*4) = o;
    }
}

// ---------------------------------------------------------------------------
// K2: scores = (Q K^T)/32 via 3xTF32 mma (fp32-grade accuracy)
//     block: 128x128 output tile, 8 warps (4x2), warp tile 32x64
// ---------------------------------------------------------------------------
__global__ void __launch_bounds__(256) scores_mma() {
    extern __shared__ unsigned su[];
    unsigned* Qh = su;
    unsigned* Ql = su + 128*PAD;
    unsigned* Kh = su + 2*128*PAD;
    unsigned* Kl = su + 3*128*PAD;

    const int b  = blockIdx.z;
    const int i0 = blockIdx.y * 128, j0 = blockIdx.x * 128;
    const int tid  = threadIdx.x;
    const int warp = tid >> 5, lane = tid & 31;
    const int g = lane >> 2, t = lane & 3;
    const int wy = warp >> 1, wx = warp & 1;

    // load Q/K tiles (128x64 each) -> hi/lo tf32 split in smem
#pragma unroll
    for (int p = 0; p < 8; p++) {
        int idx = p*256 + tid;
        int row = idx >> 4;
        int c4  = (idx & 15) * 4;
        float4 q = *(const float4*)(g_q + (size_t)(b*SS + i0 + row)*DD + c4);
        uint4 h, l;
        h.x = f2tf(q.x); l.x = f2tf(q.x - __uint_as_float(h.x));
        h.y = f2tf(q.y); l.y = f2tf(q.y - __uint_as_float(h.y));
        h.z = f2tf(q.z); l.z = f2tf(q.z - __uint_as_float(h.z));
        h.w = f2tf(q.w); l.w = f2tf(q.w - __uint_as_float(h.w));
        *(uint4*)&Qh[row*PAD + c4] = h;
        *(uint4*)&Ql[row*PAD + c4] = l;
        float4 k = *(const float4*)(g_k + (size_t)(b*SS + j0 + row)*DD + c4);
        h.x = f2tf(k.x); l.x = f2tf(k.x - __uint_as_float(h.x));
        h.y = f2tf(k.y); l.y = f2tf(k.y - __uint_as_float(h.y));
        h.z = f2tf(k.z); l.z = f2tf(k.z - __uint_as_float(h.z));
        h.w = f2tf(k.w); l.w = f2tf(k.w - __uint_as_float(h.w));
        *(uint4*)&Kh[row*PAD + c4] = h;
        *(uint4*)&Kl[row*PAD + c4] = l;
    }
    __syncthreads();

    float c[2][8][4] = {};
#pragma unroll
    for (int k8 = 0; k8 < 8; k8++) {
        const int kc = k8*8;
        unsigned ah[2][4], al[2][4];
#pragma unroll
        for (int mt = 0; mt < 2; mt++) {
            int r = wy*32 + mt*16 + g;
            ah[mt][0] = Qh[ r     *PAD + kc + t    ];
            ah[mt][1] = Qh[(r + 8)*PAD + kc + t    ];
            ah[mt][2] = Qh[ r     *PAD + kc + t + 4];
            ah[mt][3] = Qh[(r + 8)*PAD + kc + t + 4];
            al[mt][0] = Ql[ r     *PAD + kc + t    ];
            al[mt][1] = Ql[(r + 8)*PAD + kc + t    ];
            al[mt][2] = Ql[ r     *PAD + kc + t + 4];
            al[mt][3] = Ql[(r + 8)*PAD + kc + t + 4];
        }
#pragma unroll
        for (int nt = 0; nt < 8; nt++) {
            int n = wx*64 + nt*8 + g;
            unsigned bh[2], bl[2];
            bh[0] = Kh[n*PAD + kc + t];
            bh[1] = Kh[n*PAD + kc + t + 4];
            bl[0] = Kl[n*PAD + kc + t];
            bl[1] = Kl[n*PAD + kc + t + 4];
#pragma unroll
            for (int mt = 0; mt < 2; mt++) {
                mma_tf32(c[mt][nt], ah[mt], bh);   // hi*hi
                mma_tf32(c[mt][nt], ah[mt], bl);   // hi*lo
                mma_tf32(c[mt][nt], al[mt], bh);   // lo*hi
            }
        }
    }

    const float sc = 0.03125f;  // 1/sqrt(1024)
#pragma unroll
    for (int mt = 0; mt < 2; mt++) {
#pragma unroll
        for (int nt = 0; nt < 8; nt++) {
            int rrow = i0 + wy*32 + mt*16 + g;
            int ccol = j0 + wx*64 + nt*8 + 2*t;
            float2 v0 = make_float2(c[mt][nt][0]*sc, c[mt][nt][1]*sc);
            float2 v1 = make_float2(c[mt][nt][2]*sc, c[mt][nt][3]*sc);
            *(float2*)(g_scores + ((size_t)b*SS + rrow    )*SS + ccol) = v0;
            *(float2*)(g_scores + ((size_t)b*SS + rrow + 8)*SS + ccol) = v1;
        }
    }
}

// ---------------------------------------------------------------------------
// K4: fused layernorm-softmax-attention: head = softmax(ln(scores)) @ V
//     block: 64 rows x full row (2048) x D=64.  phase0: row stats (sum/sq/max)
//     phase1: exp-on-load + tf32 mma + fused expsum.  8 warps (4x2), warp 16x32
// ---------------------------------------------------------------------------
__global__ void __launch_bounds__(256) pv_mma() {
    __shared__ unsigned Ps[64*PAD];
    __shared__ unsigned Vs[64*VPAD];
    __shared__ float s_rstd[64], s_a[64], s_rsum[64];

    const int b  = blockIdx.y;
    const int i0 = blockIdx.x * 64;
    const int tid  = threadIdx.x;
    const int warp = tid >> 5, lane = tid & 31;
    const int g = lane >> 2, t = lane & 3;
    const int wy = warp >> 1, wx = warp & 1;
    const int rbase = tid >> 4;          // 0..15; thread owns rows rbase + 16p

    // ---------- phase 0: row stats over raw scores ----------
    float sm[4] = {}, sq[4] = {}, mx[4] = {-1e30f, -1e30f, -1e30f, -1e30f};
    for (int jt = 0; jt < SS; jt += 64) {
#pragma unroll
        for (int p = 0; p < 4; p++) {
            int row = rbase + 16*p;
            int c4  = (tid & 15) * 4;
            float4 s = *(const float4*)(g_scores + ((size_t)b*SS + i0 + row)*SS + jt + c4);
            sm[p] += (s.x + s.y) + (s.z + s.w);
            sq[p] += s.x*s.x + s.y*s.y + s.z*s.z + s.w*s.w;
            mx[p] = fmaxf(mx[p], fmaxf(fmaxf(s.x, s.y), fmaxf(s.z, s.w)));
        }
    }
#pragma unroll
    for (int p = 0; p < 4; p++) {
#pragma unroll
        for (int o = 8; o; o >>= 1) {
            sm[p] += __shfl_xor_sync(~0u, sm[p], o);
            sq[p] += __shfl_xor_sync(~0u, sq[p], o);
            mx[p]  = fmaxf(mx[p], __shfl_xor_sync(~0u, mx[p], o));
        }
        if ((lane & 15) == 0) {
            int row = (warp << 1) + (lane >> 4) + (p << 4);
            float mean = sm[p] * (1.f/(float)SS);
            float var  = (sq[p] - sm[p]*mean) * (1.f/(float)(SS-1));  // ddof=1
            float rstd = 1.f / (sqrtf(fmaxf(var, 0.f)) + 1e-8f);
            s_rstd[row] = rstd;
            s_a[row]    = mean*rstd + (mx[p] - mean)*rstd;
        }
    }
    __syncthreads();

    float rstd_p[4], a_p[4];
#pragma unroll
    for (int p = 0; p < 4; p++) { rstd_p[p] = s_rstd[rbase + 16*p]; a_p[p] = s_a[rbase + 16*p]; }

    // ---------- phase 1: exp + mma + expsum ----------
    float acc[4][4] = {};
    float esum[4] = {};
    for (int jt = 0; jt < SS; jt += 64) {
#pragma unroll
        for (int p = 0; p < 4; p++) {
            int row = rbase + 16*p;
            int c4  = (tid & 15) * 4;
            float4 s = *(const float4*)(g_scores + ((size_t)b*SS + i0 + row)*SS + jt + c4);
            float e0 = __expf(fmaf(s.x, rstd_p[p], -a_p[p]));
            float e1 = __expf(fmaf(s.y, rstd_p[p], -a_p[p]));
            float e2 = __expf(fmaf(s.z, rstd_p[p], -a_p[p]));
            float e3 = __expf(fmaf(s.w, rstd_p[p], -a_p[p]));
            esum[p] += (e0 + e1) + (e2 + e3);
            uint4 u = make_uint4(f2tf(e0), f2tf(e1), f2tf(e2), f2tf(e3));
            *(uint4*)&Ps[row*PAD + c4] = u;

            int krow = row;  // same pattern for V tile
            float4 v = *(const float4*)(g_v + (size_t)(b*SS + jt + krow)*DD + c4);
            uint4 uv = make_uint4(f2tf(v.x), f2tf(v.y), f2tf(v.z), f2tf(v.w));
            *(uint4*)&Vs[krow*VPAD + c4] = uv;
        }
        __syncthreads();
#pragma unroll
        for (int k8 = 0; k8 < 8; k8++) {
            const int kc = k8*8;
            unsigned a[4];
            int r = wy*16 + g;
            a[0] = Ps[ r     *PAD + kc + t    ];
            a[1] = Ps[(r + 8)*PAD + kc + t    ];
            a[2] = Ps[ r     *PAD + kc + t + 4];
            a[3] = Ps[(r + 8)*PAD + kc + t + 4];
#pragma unroll
            for (int nt = 0; nt < 4; nt++) {
                int n = wx*32 + nt*8 + g;
                unsigned bb[2];
                bb[0] = Vs[(kc + t    )*VPAD + n];
                bb[1] = Vs[(kc + t + 4)*VPAD + n];
                mma_tf32(acc[nt], a, bb);
            }
        }
        __syncthreads();
    }

    // expsum reduce -> 1/sum
#pragma unroll
    for (int p = 0; p < 4; p++) {
#pragma unroll
        for (int o = 8; o; o >>= 1) esum[p] += __shfl_xor_sync(~0u, esum[p], o);
        if ((lane & 15) == 0) {
            int row = (warp << 1) + (lane >> 4) + (p << 4);
            s_rsum[row] = 1.f / esum[p];
        }
    }
    __syncthreads();

    // scaled output
#pragma unroll
    for (int nt = 0; nt < 4; nt++) {
        int r0 = wy*16 + g, r1 = r0 + 8;
        int col = wx*32 + nt*8 + 2*t;
        float q0 = s_rsum[r0], q1 = s_rsum[r1];
        float2 v0 = make_float2(acc[nt][0]*q0, acc[nt][1]*q0);
        float2 v1 = make_float2(acc[nt][2]*q1, acc[nt][3]*q1);
        *(float2*)(g_head + (size_t)(b*SS + i0 + r0)*DD + col) = v0;
        *(float2*)(g_head + (size_t)(b*SS + i0 + r1)*DD + col) = v1;
    }
}

// ---------------------------------------------------------------------------
// K5: out = head @ W_eff + bout    [8192,64]@[64,1024]
// ---------------------------------------------------------------------------
__global__ void __launch_bounds__(256) out_kernel(const float* __restrict__ bout,
                                                  float* __restrict__ out) {
    const int mbase = blockIdx.x * 64;
    const int nbase = blockIdx.y * 64;
    __shared__ float Hs[64][65];                 // k-major
    __shared__ __align__(16) float Ws[64][64];
    const int tid = threadIdx.x;
#pragma unroll
    for (int p = 0; p < 4; p++) {
        int m  = (tid >> 4) + p*16;
        int d4 = (tid & 15) * 4;
        float4 h = *(const float4*)(g_head + (size_t)(mbase + m)*DD + d4);
        Hs[d4+0][m] = h.x; Hs[d4+1][m] = h.y; Hs[d4+2][m] = h.z; Hs[d4+3][m] = h.w;
        int k  = (tid >> 4) + p*16;
        int n4 = (tid & 15) * 4;
        *(float4*)&Ws[k][n4] = *(const float4*)(g_weff + (size_t)k*HID + nbase + n4);
    }
    __syncthreads();
    const int tx = tid & 15, ty = tid >> 4;
    float acc[4][4] = {};
#pragma unroll
    for (int k = 0; k < 64; k++) {
        float a[4];
#pragma unroll
        for (int i = 0; i < 4; i++) a[i] = Hs[k][ty*4 + i];
        float4 w = *(const float4*)&Ws[k][tx*4];
        acc[0][0] += a[0]*w.x; acc[0][1] += a[0]*w.y; acc[0][2] += a[0]*w.z; acc[0][3] += a[0]*w.w;
        acc[1][0] += a[1]*w.x; acc[1][1] += a[1]*w.y; acc[1][2] += a[1]*w.z; acc[1][3] += a[1]*w.w;
        acc[2][0] += a[2]*w.x; acc[2][1] += a[2]*w.y; acc[2][2] += a[2]*w.z; acc[2][3] += a[2]*w.w;
        acc[3][0] += a[3]*w.x; acc[3][1] += a[3]*w.y; acc[3][2] += a[3]*w.z; acc[3][3] += a[3]*w.w;
    }
    float4 bb = *(const float4*)(bout + nbase + tx*4);
#pragma unroll
    for (int i = 0; i < 4; i++) {
        float4 o = make_float4(acc[i][0]+bb.x, acc[i][1]+bb.y, acc[i][2]+bb.z, acc[i][3]+bb.w);
        *(float4*)(out + (size_t)(mbase + ty*4 + i)*HID + nbase + tx*4) = o;
    }
}

// ---------------------------------------------------------------------------
extern "C" void kernel_launch(void* const* d_in, const int* in_sizes, int n_in,
                              void* d_out, int out_size) {
    (void)in_sizes; (void)n_in; (void)out_size;
    const float* query = (const float*)d_in[0];
    const float* key   = (const float*)d_in[1];
    const float* value = (const float*)d_in[2];
    // d_in[3] mask: adding -1e-32 is a numeric no-op in fp32 -> skipped
    const float* Wq   = (const float*)d_in[4];
    const float* bq   = (const float*)d_in[5];
    const float* Wk   = (const float*)d_in[6];
    const float* bk   = (const float*)d_in[7];
    const float* Wv   = (const float*)d_in[8];
    const float* bv   = (const float*)d_in[9];
    const float* Wout = (const float*)d_in[10];
    const float* bout = (const float*)d_in[11];
    // d_in[12] seq_mask == 0 -> no causal mask
    float* out = (float*)d_out;

    const int scores_smem = 4 * 128 * PAD * 4;  // 139264 B
    cudaFuncSetAttribute(scores_mma, cudaFuncAttributeMaxDynamicSharedMemorySize, scores_smem);

    weff_kernel<<<256, 256>>>(Wout);
    proj_kernel<<<dim3(128, 3), 256>>>(query, key, value, Wq, Wk, Wv, bq, bk, bv);
    scores_mma<<<dim3(16, 16, 4), 256, scores_smem>>>();
    pv_mma<<<dim3(32, 4), 256>>>();
    out_kernel<<<dim3(128, 16), 256>>>(bout, out);
}

// round 4
// speedup vs baseline: 1.1146x; 1.1146x over previous
#include <cuda_runtime.h>
#include <math.h>

#define BB 4
#define SS 2048
#define HID 1024
#define DD 64
#define RR (BB*SS)   // 8192 rows total
#define PAD 68       // 64-wide fp32/u32 tiles: bank = 4*row+col -> conflict-free A frags
#define XPAD 36      // 32-wide tiles
#define VPAD 72      // k-major 64-wide B tiles: bank = 8*k+n -> conflict-free B frags
#define WPAD 136     // k-major 128-wide B tiles: bank = 8*k+n
#define PPAD 132     // 128-wide P tile (A-frag): bank = 4*row+col

// ---- scratch (static device arrays; no allocation) ----
static __device__ float g_q[RR*DD];
static __device__ float g_k[RR*DD];
static __device__ float g_v[RR*DD];
static __device__ float g_head[RR*DD];
static __device__ float g_scores[(size_t)RR*SS];   // 67 MB
static __device__ float g_weff[DD*HID];

// ---------------------------------------------------------------------------
// helpers
// ---------------------------------------------------------------------------
__device__ __forceinline__ unsigned f2tf(float x) {
    unsigned r;
    asm("cvt.rna.tf32.f32 %0, %1;" : "=r"(r) : "f"(x));
    return r;
}
__device__ __forceinline__ void hilo(float x, unsigned& h, unsigned& l) {
    h = f2tf(x);
    l = f2tf(x - __uint_as_float(h));
}
__device__ __forceinline__ void mma_tf32(float* c, const unsigned* a, const unsigned* b) {
    asm volatile(
        "mma.sync.aligned.m16n8k8.row.col.f32.tf32.tf32.f32 "
        "{%0,%1,%2,%3}, {%4,%5,%6,%7}, {%8,%9}, {%0,%1,%2,%3};"
        : "+f"(c[0]), "+f"(c[1]), "+f"(c[2]), "+f"(c[3])
        : "r"(a[0]), "r"(a[1]), "r"(a[2]), "r"(a[3]), "r"(b[0]), "r"(b[1]));
}

// ---------------------------------------------------------------------------
// K0: W_eff[r][c] = sum_h Wout[h*64+r][c]
// ---------------------------------------------------------------------------
__global__ void weff_kernel(const float* __restrict__ Wout) {
    int idx = blockIdx.x * 256 + threadIdx.x;
    int r = idx >> 10, c = idx & 1023;
    float s = 0.f;
#pragma unroll
    for (int h = 0; h < 16; h++) s += Wout[(size_t)(h*64 + r)*HID + c];
    g_weff[idx] = s;
}

// ---------------------------------------------------------------------------
// K1: Q/K/V projections via 3xTF32 mma: [8192,1024]@[1024,64]+b
//     block: 128 rows x 64 cols, K-chunk 32; 8 warps (4x2), warp 32x32
// ---------------------------------------------------------------------------
__global__ void __launch_bounds__(256) proj_mma(
    const float* __restrict__ xq, const float* __restrict__ xk, const float* __restrict__ xv,
    const float* __restrict__ Wq, const float* __restrict__ Wk, const float* __restrict__ Wv,
    const float* __restrict__ bq, const float* __restrict__ bk, const float* __restrict__ bv)
{
    extern __shared__ unsigned sm[];
    unsigned* Xh = sm;
    unsigned* Xl = sm + 128*XPAD;
    unsigned* Wh = sm + 2*128*XPAD;
    unsigned* Wl = sm + 2*128*XPAD + 32*VPAD;

    const int which = blockIdx.y;
    const float* X    = which == 0 ? xq : which == 1 ? xk : xv;
    const float* W    = which == 0 ? Wq : which == 1 ? Wk : Wv;
    const float* bias = which == 0 ? bq : which == 1 ? bk : bv;
    float*       O    = which == 0 ? g_q : which == 1 ? g_k : g_v;

    const int mbase = blockIdx.x * 128;
    const int tid  = threadIdx.x;
    const int warp = tid >> 5, lane = tid & 31;
    const int g = lane >> 2, t = lane & 3;
    const int wy = warp >> 1, wx = warp & 1;

    float acc[2][4][4] = {};

    for (int kk = 0; kk < HID; kk += 32) {
        // X tile 128x32 -> hi/lo
#pragma unroll
        for (int p = 0; p < 4; p++) {
            int idx = p*256 + tid;
            int row = idx >> 3, c4 = (idx & 7) * 4;
            float4 v = *(const float4*)(X + (size_t)(mbase + row)*HID + kk + c4);
            uint4 h, l;
            hilo(v.x, h.x, l.x); hilo(v.y, h.y, l.y);
            hilo(v.z, h.z, l.z); hilo(v.w, h.w, l.w);
            *(uint4*)&Xh[row*XPAD + c4] = h;
            *(uint4*)&Xl[row*XPAD + c4] = l;
        }
        // W tile 32x64 -> hi/lo (k-major rows)
#pragma unroll
        for (int p = 0; p < 2; p++) {
            int idx = p*256 + tid;
            int k = idx >> 4, n4 = (idx & 15) * 4;
            float4 v = *(const float4*)(W + (size_t)(kk + k)*DD + n4);
            uint4 h, l;
            hilo(v.x, h.x, l.x); hilo(v.y, h.y, l.y);
            hilo(v.z, h.z, l.z); hilo(v.w, h.w, l.w);
            *(uint4*)&Wh[k*VPAD + n4] = h;
            *(uint4*)&Wl[k*VPAD + n4] = l;
        }
        __syncthreads();
#pragma unroll
        for (int k8 = 0; k8 < 4; k8++) {
            const int kc = k8*8;
            unsigned ah[2][4], al[2][4];
#pragma unroll
            for (int mt = 0; mt < 2; mt++) {
                int r = wy*32 + mt*16 + g;
                ah[mt][0] = Xh[ r     *XPAD + kc + t    ];
                ah[mt][1] = Xh[(r + 8)*XPAD + kc + t    ];
                ah[mt][2] = Xh[ r     *XPAD + kc + t + 4];
                ah[mt][3] = Xh[(r + 8)*XPAD + kc + t + 4];
                al[mt][0] = Xl[ r     *XPAD + kc + t    ];
                al[mt][1] = Xl[(r + 8)*XPAD + kc + t    ];
                al[mt][2] = Xl[ r     *XPAD + kc + t + 4];
                al[mt][3] = Xl[(r + 8)*XPAD + kc + t + 4];
            }
#pragma unroll
            for (int nt = 0; nt < 4; nt++) {
                int n = wx*32 + nt*8 + g;
                unsigned bh[2], bl[2];
                bh[0] = Wh[(kc + t    )*VPAD + n];
                bh[1] = Wh[(kc + t + 4)*VPAD + n];
                bl[0] = Wl[(kc + t    )*VPAD + n];
                bl[1] = Wl[(kc + t + 4)*VPAD + n];
#pragma unroll
                for (int mt = 0; mt < 2; mt++) {
                    mma_tf32(acc[mt][nt], ah[mt], bh);
                    mma_tf32(acc[mt][nt], ah[mt], bl);
                    mma_tf32(acc[mt][nt], al[mt], bh);
                }
            }
        }
        __syncthreads();
    }
#pragma unroll
    for (int mt = 0; mt < 2; mt++) {
#pragma unroll
        for (int nt = 0; nt < 4; nt++) {
            int r = mbase + wy*32 + mt*16 + g;
            int col = wx*32 + nt*8 + 2*t;
            float b0 = bias[col], b1 = bias[col+1];
            *(float2*)(O + (size_t)r*DD + col)       = make_float2(acc[mt][nt][0]+b0, acc[mt][nt][1]+b1);
            *(float2*)(O + (size_t)(r + 8)*DD + col) = make_float2(acc[mt][nt][2]+b0, acc[mt][nt][3]+b1);
        }
    }
}

// ---------------------------------------------------------------------------
// K2: scores = (Q K^T)/32 via 3xTF32 mma
//     block: 128x64 output tile (smem 104KB -> 2 blocks/SM), 8 warps (4x2)
// ---------------------------------------------------------------------------
__global__ void __launch_bounds__(256) scores_mma() {
    extern __shared__ unsigned su[];
    unsigned* Qh = su;
    unsigned* Ql = su + 128*PAD;
    unsigned* Kh = su + 2*128*PAD;
    unsigned* Kl = su + 2*128*PAD + 64*PAD;

    const int b  = blockIdx.z;
    const int i0 = blockIdx.y * 128, j0 = blockIdx.x * 64;
    const int tid  = threadIdx.x;
    const int warp = tid >> 5, lane = tid & 31;
    const int g = lane >> 2, t = lane & 3;
    const int wy = warp >> 1, wx = warp & 1;

    // Q tile 128x64 -> hi/lo
#pragma unroll
    for (int p = 0; p < 8; p++) {
        int idx = p*256 + tid;
        int row = idx >> 4, c4 = (idx & 15) * 4;
        float4 q = *(const float4*)(g_q + (size_t)(b*SS + i0 + row)*DD + c4);
        uint4 h, l;
        hilo(q.x, h.x, l.x); hilo(q.y, h.y, l.y);
        hilo(q.z, h.z, l.z); hilo(q.w, h.w, l.w);
        *(uint4*)&Qh[row*PAD + c4] = h;
        *(uint4*)&Ql[row*PAD + c4] = l;
    }
    // K tile 64x64 -> hi/lo
#pragma unroll
    for (int p = 0; p < 4; p++) {
        int idx = p*256 + tid;
        int row = idx >> 4, c4 = (idx & 15) * 4;
        float4 k = *(const float4*)(g_k + (size_t)(b*SS + j0 + row)*DD + c4);
        uint4 h, l;
        hilo(k.x, h.x, l.x); hilo(k.y, h.y, l.y);
        hilo(k.z, h.z, l.z); hilo(k.w, h.w, l.w);
        *(uint4*)&Kh[row*PAD + c4] = h;
        *(uint4*)&Kl[row*PAD + c4] = l;
    }
    __syncthreads();

    float c[2][4][4] = {};
#pragma unroll
    for (int k8 = 0; k8 < 8; k8++) {
        const int kc = k8*8;
        unsigned ah[2][4], al[2][4];
#pragma unroll
        for (int mt = 0; mt < 2; mt++) {
            int r = wy*32 + mt*16 + g;
            ah[mt][0] = Qh[ r     *PAD + kc + t    ];
            ah[mt][1] = Qh[(r + 8)*PAD + kc + t    ];
            ah[mt][2] = Qh[ r     *PAD + kc + t + 4];
            ah[mt][3] = Qh[(r + 8)*PAD + kc + t + 4];
            al[mt][0] = Ql[ r     *PAD + kc + t    ];
            al[mt][1] = Ql[(r + 8)*PAD + kc + t    ];
            al[mt][2] = Ql[ r     *PAD + kc + t + 4];
            al[mt][3] = Ql[(r + 8)*PAD + kc + t + 4];
        }
#pragma unroll
        for (int nt = 0; nt < 4; nt++) {
            int n = wx*32 + nt*8 + g;
            unsigned bh[2], bl[2];
            bh[0] = Kh[n*PAD + kc + t];
            bh[1] = Kh[n*PAD + kc + t + 4];
            bl[0] = Kl[n*PAD + kc + t];
            bl[1] = Kl[n*PAD + kc + t + 4];
#pragma unroll
            for (int mt = 0; mt < 2; mt++) {
                mma_tf32(c[mt][nt], ah[mt], bh);
                mma_tf32(c[mt][nt], ah[mt], bl);
                mma_tf32(c[mt][nt], al[mt], bh);
            }
        }
    }

    const float sc = 0.03125f;  // 1/sqrt(1024)
#pragma unroll
    for (int mt = 0; mt < 2; mt++) {
#pragma unroll
        for (int nt = 0; nt < 4; nt++) {
            int rrow = i0 + wy*32 + mt*16 + g;
            int ccol = j0 + wx*32 + nt*8 + 2*t;
            *(float2*)(g_scores + ((size_t)b*SS + rrow    )*SS + ccol) =
                make_float2(c[mt][nt][0]*sc, c[mt][nt][1]*sc);
            *(float2*)(g_scores + ((size_t)b*SS + rrow + 8)*SS + ccol) =
                make_float2(c[mt][nt][2]*sc, c[mt][nt][3]*sc);
        }
    }
}

// ---------------------------------------------------------------------------
// K4: fused layernorm-softmax-attention: head = softmax(ln(scores)) @ V
//     block: 32 rows x full row x D=64; jt step 128; 8 warps (2x4), warp 16x16
// ---------------------------------------------------------------------------
__global__ void __launch_bounds__(256) pv_mma() {
    extern __shared__ unsigned pvsm[];
    unsigned* Ps = pvsm;               // [32][PPAD]
    unsigned* Vs = pvsm + 32*PPAD;     // [128][VPAD]
    __shared__ float s_rstd[32], s_a[32], s_rsum[32];

    const int b  = blockIdx.y;
    const int i0 = blockIdx.x * 32;
    const int tid  = threadIdx.x;
    const int warp = tid >> 5, lane = tid & 31;
    const int g = lane >> 2, t = lane & 3;
    const int wy = warp >> 2, wx = warp & 3;
    const int myrow = tid >> 3;        // 0..31 (thread owns one row for stats)
    const int lane8 = tid & 7;
    const float* srow = g_scores + ((size_t)b*SS + i0 + myrow)*SS;

    // ---------- phase 0: row stats over raw scores ----------
    float sm = 0.f, sq = 0.f, mx = -1e30f;
    for (int jt = 0; jt < SS; jt += 128) {
#pragma unroll
        for (int q = 0; q < 4; q++) {
            float4 s = *(const float4*)(srow + jt + (lane8 + 8*q)*4);
            sm += (s.x + s.y) + (s.z + s.w);
            sq += s.x*s.x + s.y*s.y + s.z*s.z + s.w*s.w;
            mx = fmaxf(mx, fmaxf(fmaxf(s.x, s.y), fmaxf(s.z, s.w)));
        }
    }
#pragma unroll
    for (int o = 4; o; o >>= 1) {
        sm += __shfl_xor_sync(~0u, sm, o);
        sq += __shfl_xor_sync(~0u, sq, o);
        mx  = fmaxf(mx, __shfl_xor_sync(~0u, mx, o));
    }
    if (lane8 == 0) {
        float mean = sm * (1.f/(float)SS);
        float var  = (sq - sm*mean) * (1.f/(float)(SS-1));   // ddof=1
        float rstd = 1.f / (sqrtf(fmaxf(var, 0.f)) + 1e-8f);
        s_rstd[myrow] = rstd;
        s_a[myrow]    = mean*rstd + (mx - mean)*rstd;
    }
    __syncthreads();
    const float rstd = s_rstd[myrow], aa = s_a[myrow];

    // ---------- phase 1: exp + mma + fused expsum ----------
    float acc[2][4] = {};
    float esum = 0.f;
    for (int jt = 0; jt < SS; jt += 128) {
#pragma unroll
        for (int q = 0; q < 4; q++) {
            int c4 = (lane8 + 8*q)*4;
            float4 s = *(const float4*)(srow + jt + c4);
            float e0 = __expf(fmaf(s.x, rstd, -aa));
            float e1 = __expf(fmaf(s.y, rstd, -aa));
            float e2 = __expf(fmaf(s.z, rstd, -aa));
            float e3 = __expf(fmaf(s.w, rstd, -aa));
            esum += (e0 + e1) + (e2 + e3);
            *(uint4*)&Ps[myrow*PPAD + c4] = make_uint4(f2tf(e0), f2tf(e1), f2tf(e2), f2tf(e3));
        }
#pragma unroll
        for (int p = 0; p < 8; p++) {
            int idx = p*256 + tid;
            int jl = idx >> 4, n4 = (idx & 15) * 4;
            float4 v = *(const float4*)(g_v + (size_t)(b*SS + jt + jl)*DD + n4);
            *(uint4*)&Vs[jl*VPAD + n4] = make_uint4(f2tf(v.x), f2tf(v.y), f2tf(v.z), f2tf(v.w));
        }
        __syncthreads();
#pragma unroll
        for (int k8 = 0; k8 < 16; k8++) {
            const int kc = k8*8;
            unsigned a[4];
            int r = wy*16 + g;
            a[0] = Ps[ r     *PPAD + kc + t    ];
            a[1] = Ps[(r + 8)*PPAD + kc + t    ];
            a[2] = Ps[ r     *PPAD + kc + t + 4];
            a[3] = Ps[(r + 8)*PPAD + kc + t + 4];
#pragma unroll
            for (int nt = 0; nt < 2; nt++) {
                int n = wx*16 + nt*8 + g;
                unsigned bb[2];
                bb[0] = Vs[(kc + t    )*VPAD + n];
                bb[1] = Vs[(kc + t + 4)*VPAD + n];
                mma_tf32(acc[nt], a, bb);
            }
        }
        __syncthreads();
    }

#pragma unroll
    for (int o = 4; o; o >>= 1) esum += __shfl_xor_sync(~0u, esum, o);
    if (lane8 == 0) s_rsum[myrow] = 1.f / esum;
    __syncthreads();

    int r0 = wy*16 + g, r1 = r0 + 8;
    float q0 = s_rsum[r0], q1 = s_rsum[r1];
#pragma unroll
    for (int nt = 0; nt < 2; nt++) {
        int col = wx*16 + nt*8 + 2*t;
        *(float2*)(g_head + (size_t)(b*SS + i0 + r0)*DD + col) =
            make_float2(acc[nt][0]*q0, acc[nt][1]*q0);
        *(float2*)(g_head + (size_t)(b*SS + i0 + r1)*DD + col) =
            make_float2(acc[nt][2]*q1, acc[nt][3]*q1);
    }
}

// ---------------------------------------------------------------------------
// K5: out = head @ W_eff + bout via 3xTF32 mma: [8192,64]@[64,1024]
//     block: 64 rows x 128 cols, K=64 single shot; 8 warps (4x2), warp 16x64
// ---------------------------------------------------------------------------
__global__ void __launch_bounds__(256) out_mma(const float* __restrict__ bout,
                                               float* __restrict__ out) {
    extern __shared__ unsigned om[];
    unsigned* Hh = om;
    unsigned* Hl = om + 64*PAD;
    unsigned* Wh = om + 2*64*PAD;
    unsigned* Wl = om + 2*64*PAD + 64*WPAD;

    const int mbase = blockIdx.x * 64;
    const int nbase = blockIdx.y * 128;
    const int tid  = threadIdx.x;
    const int warp = tid >> 5, lane = tid & 31;
    const int g = lane >> 2, t = lane & 3;
    const int wy = warp >> 1, wx = warp & 1;

    // head tile 64x64 -> hi/lo
#pragma unroll
    for (int p = 0; p < 4; p++) {
        int idx = p*256 + tid;
        int row = idx >> 4, c4 = (idx & 15) * 4;
        float4 h4 = *(const float4*)(g_head + (size_t)(mbase + row)*DD + c4);
        uint4 h, l;
        hilo(h4.x, h.x, l.x); hilo(h4.y, h.y, l.y);
        hilo(h4.z, h.z, l.z); hilo(h4.w, h.w, l.w);
        *(uint4*)&Hh[row*PAD + c4] = h;
        *(uint4*)&Hl[row*PAD + c4] = l;
    }
    // Weff tile 64x128 -> hi/lo (k-major)
#pragma unroll
    for (int p = 0; p < 8; p++) {
        int idx = p*256 + tid;
        int k = idx >> 5, n4 = (idx & 31) * 4;
        float4 w4 = *(const float4*)(g_weff + (size_t)k*HID + nbase + n4);
        uint4 h, l;
        hilo(w4.x, h.x, l.x); hilo(w4.y, h.y, l.y);
        hilo(w4.z, h.z, l.z); hilo(w4.w, h.w, l.w);
        *(uint4*)&Wh[k*WPAD + n4] = h;
        *(uint4*)&Wl[k*WPAD + n4] = l;
    }
    __syncthreads();

    float acc[8][4] = {};
#pragma unroll
    for (int k8 = 0; k8 < 8; k8++) {
        const int kc = k8*8;
        unsigned ah[4], al[4];
        int r = wy*16 + g;
        ah[0] = Hh[ r     *PAD + kc + t    ];
        ah[1] = Hh[(r + 8)*PAD + kc + t    ];
        ah[2] = Hh[ r     *PAD + kc + t + 4];
        ah[3] = Hh[(r + 8)*PAD + kc + t + 4];
        al[0] = Hl[ r     *PAD + kc + t    ];
        al[1] = Hl[(r + 8)*PAD + kc + t    ];
        al[2] = Hl[ r     *PAD + kc + t + 4];
        al[3] = Hl[(r + 8)*PAD + kc + t + 4];
#pragma unroll
        for (int nt = 0; nt < 8; nt++) {
            int n = wx*64 + nt*8 + g;
            unsigned bh[2], bl[2];
            bh[0] = Wh[(kc + t    )*WPAD + n];
            bh[1] = Wh[(kc + t + 4)*WPAD + n];
            bl[0] = Wl[(kc + t    )*WPAD + n];
            bl[1] = Wl[(kc + t + 4)*WPAD + n];
            mma_tf32(acc[nt], ah, bh);
            mma_tf32(acc[nt], ah, bl);
            mma_tf32(acc[nt], al, bh);
        }
    }

    int r0 = mbase + wy*16 + g, r1 = r0 + 8;
#pragma unroll
    for (int nt = 0; nt < 8; nt++) {
        int col = nbase + wx*64 + nt*8 + 2*t;
        float b0 = bout[col], b1 = bout[col+1];
        *(float2*)(out + (size_t)r0*HID + col) = make_float2(acc[nt][0]+b0, acc[nt][1]+b1);
        *(float2*)(out + (size_t)r1*HID + col) = make_float2(acc[nt][2]+b0, acc[nt][3]+b1);
    }
}

// ---------------------------------------------------------------------------
extern "C" void kernel_launch(void* const* d_in, const int* in_sizes, int n_in,
                              void* d_out, int out_size) {
    (void)in_sizes; (void)n_in; (void)out_size;
    const float* query = (const float*)d_in[0];
    const float* key   = (const float*)d_in[1];
    const float* value = (const float*)d_in[2];
    // d_in[3] mask: adding -1e-32 is a numeric no-op in fp32 -> skipped
    const float* Wq   = (const float*)d_in[4];
    const float* bq   = (const float*)d_in[5];
    const float* Wk   = (const float*)d_in[6];
    const float* bk   = (const float*)d_in[7];
    const float* Wv   = (const float*)d_in[8];
    const float* bv   = (const float*)d_in[9];
    const float* Wout = (const float*)d_in[10];
    const float* bout = (const float*)d_in[11];
    // d_in[12] seq_mask == 0 -> no causal mask
    float* out = (float*)d_out;

    const int proj_smem   = (2*128*XPAD + 2*32*VPAD) * 4;        // 55296 B
    const int scores_smem = (2*128*PAD + 2*64*PAD) * 4;          // 104448 B
    const int pv_smem     = (32*PPAD + 128*VPAD) * 4;            // 53760 B
    const int out_smem    = (2*64*PAD + 2*64*WPAD) * 4;          // 104448 B
    cudaFuncSetAttribute(proj_mma,   cudaFuncAttributeMaxDynamicSharedMemorySize, proj_smem);
    cudaFuncSetAttribute(scores_mma, cudaFuncAttributeMaxDynamicSharedMemorySize, scores_smem);
    cudaFuncSetAttribute(pv_mma,     cudaFuncAttributeMaxDynamicSharedMemorySize, pv_smem);
    cudaFuncSetAttribute(out_mma,    cudaFuncAttributeMaxDynamicSharedMemorySize, out_smem);

    weff_kernel<<<256, 256>>>(Wout);
    proj_mma<<<dim3(64, 3), 256, proj_smem>>>(query, key, value, Wq, Wk, Wv, bq, bk, bv);
    scores_mma<<<dim3(32, 16, 4), 256, scores_smem>>>();
    pv_mma<<<dim3(64, 4), 256, pv_smem>>>();
    out_mma<<<dim3(128, 8), 256, out_smem>>>(bout, out);
}

// round 5
// speedup vs baseline: 1.2186x; 1.0932x over previous
#include <cuda_runtime.h>
#include <math.h>

#define BB 4
#define SS 2048
#define HID 1024
#define DD 64
#define RR (BB*SS)   // 8192 rows total
#define NJT 32       // number of 64-wide j-tiles in scores
#define NSPLIT 4     // pv j-splits
#define PAD 68       // 64-wide u32 tiles: bank = 4*row+col -> conflict-free A frags
#define XPAD 36      // 32-wide tiles
#define VPAD 72      // k-major 64-wide B tiles: bank = 8*k+n -> conflict-free B frags
#define WPAD 136     // k-major 128-wide B tiles
#define PPAD 132     // 128-wide P tile (A-frag)

// ---- scratch (static device arrays; no allocation) ----
static __device__ float g_q[RR*DD];
static __device__ float g_k[RR*DD];
static __device__ float g_v[RR*DD];
static __device__ float g_scores[(size_t)RR*SS];   // 67 MB
static __device__ float g_weff[DD*HID];
static __device__ float g_ssum[NJT*RR];            // per-jtile row partial sums
static __device__ float g_ssq [NJT*RR];
static __device__ float g_smx [NJT*RR];
static __device__ float g_rstd[RR];
static __device__ float g_a[RR];
static __device__ float g_esump[NSPLIT*RR];        // expsum partials per split
static __device__ float g_headp[(size_t)NSPLIT*RR*DD]; // unnormalized head partials

// ---------------------------------------------------------------------------
// helpers
// ---------------------------------------------------------------------------
__device__ __forceinline__ unsigned f2tf(float x) {
    unsigned r;
    asm("cvt.rna.tf32.f32 %0, %1;" : "=r"(r) : "f"(x));
    return r;
}
__device__ __forceinline__ void hilo(float x, unsigned& h, unsigned& l) {
    h = f2tf(x);
    l = f2tf(x - __uint_as_float(h));
}
__device__ __forceinline__ void mma_tf32(float* c, const unsigned* a, const unsigned* b) {
    asm volatile(
        "mma.sync.aligned.m16n8k8.row.col.f32.tf32.tf32.f32 "
        "{%0,%1,%2,%3}, {%4,%5,%6,%7}, {%8,%9}, {%0,%1,%2,%3};"
        : "+f"(c[0]), "+f"(c[1]), "+f"(c[2]), "+f"(c[3])
        : "r"(a[0]), "r"(a[1]), "r"(a[2]), "r"(a[3]), "r"(b[0]), "r"(b[1]));
}

// ---------------------------------------------------------------------------
// K0: W_eff[r][c] = sum_h Wout[h*64+r][c]
// ---------------------------------------------------------------------------
__global__ void weff_kernel(const float* __restrict__ Wout) {
    int idx = blockIdx.x * 256 + threadIdx.x;
    int r = idx >> 10, c = idx & 1023;
    float s = 0.f;
#pragma unroll
    for (int h = 0; h < 16; h++) s += Wout[(size_t)(h*64 + r)*HID + c];
    g_weff[idx] = s;
}

// ---------------------------------------------------------------------------
// K1: Q/K/V projections via 3xTF32 mma: [8192,1024]@[1024,64]+b
// ---------------------------------------------------------------------------
__global__ void __launch_bounds__(256) proj_mma(
    const float* __restrict__ xq, const float* __restrict__ xk, const float* __restrict__ xv,
    const float* __restrict__ Wq, const float* __restrict__ Wk, const float* __restrict__ Wv,
    const float* __restrict__ bq, const float* __restrict__ bk, const float* __restrict__ bv)
{
    extern __shared__ unsigned sm[];
    unsigned* Xh = sm;
    unsigned* Xl = sm + 128*XPAD;
    unsigned* Wh = sm + 2*128*XPAD;
    unsigned* Wl = sm + 2*128*XPAD + 32*VPAD;

    const int which = blockIdx.y;
    const float* X    = which == 0 ? xq : which == 1 ? xk : xv;
    const float* W    = which == 0 ? Wq : which == 1 ? Wk : Wv;
    const float* bias = which == 0 ? bq : which == 1 ? bk : bv;
    float*       O    = which == 0 ? g_q : which == 1 ? g_k : g_v;

    const int mbase = blockIdx.x * 128;
    const int tid  = threadIdx.x;
    const int warp = tid >> 5, lane = tid & 31;
    const int g = lane >> 2, t = lane & 3;
    const int wy = warp >> 1, wx = warp & 1;

    float acc[2][4][4] = {};

    for (int kk = 0; kk < HID; kk += 32) {
#pragma unroll
        for (int p = 0; p < 4; p++) {
            int idx = p*256 + tid;
            int row = idx >> 3, c4 = (idx & 7) * 4;
            float4 v = *(const float4*)(X + (size_t)(mbase + row)*HID + kk + c4);
            uint4 h, l;
            hilo(v.x, h.x, l.x); hilo(v.y, h.y, l.y);
            hilo(v.z, h.z, l.z); hilo(v.w, h.w, l.w);
            *(uint4*)&Xh[row*XPAD + c4] = h;
            *(uint4*)&Xl[row*XPAD + c4] = l;
        }
#pragma unroll
        for (int p = 0; p < 2; p++) {
            int idx = p*256 + tid;
            int k = idx >> 4, n4 = (idx & 15) * 4;
            float4 v = *(const float4*)(W + (size_t)(kk + k)*DD + n4);
            uint4 h, l;
            hilo(v.x, h.x, l.x); hilo(v.y, h.y, l.y);
            hilo(v.z, h.z, l.z); hilo(v.w, h.w, l.w);
            *(uint4*)&Wh[k*VPAD + n4] = h;
            *(uint4*)&Wl[k*VPAD + n4] = l;
        }
        __syncthreads();
#pragma unroll
        for (int k8 = 0; k8 < 4; k8++) {
            const int kc = k8*8;
            unsigned ah[2][4], al[2][4];
#pragma unroll
            for (int mt = 0; mt < 2; mt++) {
                int r = wy*32 + mt*16 + g;
                ah[mt][0] = Xh[ r     *XPAD + kc + t    ];
                ah[mt][1] = Xh[(r + 8)*XPAD + kc + t    ];
                ah[mt][2] = Xh[ r     *XPAD + kc + t + 4];
                ah[mt][3] = Xh[(r + 8)*XPAD + kc + t + 4];
                al[mt][0] = Xl[ r     *XPAD + kc + t    ];
                al[mt][1] = Xl[(r + 8)*XPAD + kc + t    ];
                al[mt][2] = Xl[ r     *XPAD + kc + t + 4];
                al[mt][3] = Xl[(r + 8)*XPAD + kc + t + 4];
            }
#pragma unroll
            for (int nt = 0; nt < 4; nt++) {
                int n = wx*32 + nt*8 + g;
                unsigned bh[2], bl[2];
                bh[0] = Wh[(kc + t    )*VPAD + n];
                bh[1] = Wh[(kc + t + 4)*VPAD + n];
                bl[0] = Wl[(kc + t    )*VPAD + n];
                bl[1] = Wl[(kc + t + 4)*VPAD + n];
#pragma unroll
                for (int mt = 0; mt < 2; mt++) {
                    mma_tf32(acc[mt][nt], ah[mt], bh);
                    mma_tf32(acc[mt][nt], ah[mt], bl);
                    mma_tf32(acc[mt][nt], al[mt], bh);
                }
            }
        }
        __syncthreads();
    }
#pragma unroll
    for (int mt = 0; mt < 2; mt++) {
#pragma unroll
        for (int nt = 0; nt < 4; nt++) {
            int r = mbase + wy*32 + mt*16 + g;
            int col = wx*32 + nt*8 + 2*t;
            float b0 = bias[col], b1 = bias[col+1];
            *(float2*)(O + (size_t)r*DD + col)       = make_float2(acc[mt][nt][0]+b0, acc[mt][nt][1]+b1);
            *(float2*)(O + (size_t)(r + 8)*DD + col) = make_float2(acc[mt][nt][2]+b0, acc[mt][nt][3]+b1);
        }
    }
}

// ---------------------------------------------------------------------------
// K2: scores = (Q K^T)/32 via 3xTF32 mma  + fused per-row stats partials
//     block: 128x64 output tile; per-jtile row stats -> g_ssum/g_ssq/g_smx
// ---------------------------------------------------------------------------
__global__ void __launch_bounds__(256) scores_mma() {
    extern __shared__ unsigned su[];
    unsigned* Qh = su;
    unsigned* Ql = su + 128*PAD;
    unsigned* Kh = su + 2*128*PAD;
    unsigned* Kl = su + 2*128*PAD + 64*PAD;

    const int b  = blockIdx.z;
    const int i0 = blockIdx.y * 128, j0 = blockIdx.x * 64;
    const int tid  = threadIdx.x;
    const int warp = tid >> 5, lane = tid & 31;
    const int g = lane >> 2, t = lane & 3;
    const int wy = warp >> 1, wx = warp & 1;

#pragma unroll
    for (int p = 0; p < 8; p++) {
        int idx = p*256 + tid;
        int row = idx >> 4, c4 = (idx & 15) * 4;
        float4 q = *(const float4*)(g_q + (size_t)(b*SS + i0 + row)*DD + c4);
        uint4 h, l;
        hilo(q.x, h.x, l.x); hilo(q.y, h.y, l.y);
        hilo(q.z, h.z, l.z); hilo(q.w, h.w, l.w);
        *(uint4*)&Qh[row*PAD + c4] = h;
        *(uint4*)&Ql[row*PAD + c4] = l;
    }
#pragma unroll
    for (int p = 0; p < 4; p++) {
        int idx = p*256 + tid;
        int row = idx >> 4, c4 = (idx & 15) * 4;
        float4 k = *(const float4*)(g_k + (size_t)(b*SS + j0 + row)*DD + c4);
        uint4 h, l;
        hilo(k.x, h.x, l.x); hilo(k.y, h.y, l.y);
        hilo(k.z, h.z, l.z); hilo(k.w, h.w, l.w);
        *(uint4*)&Kh[row*PAD + c4] = h;
        *(uint4*)&Kl[row*PAD + c4] = l;
    }
    __syncthreads();

    float c[2][4][4] = {};
#pragma unroll
    for (int k8 = 0; k8 < 8; k8++) {
        const int kc = k8*8;
        unsigned ah[2][4], al[2][4];
#pragma unroll
        for (int mt = 0; mt < 2; mt++) {
            int r = wy*32 + mt*16 + g;
            ah[mt][0] = Qh[ r     *PAD + kc + t    ];
            ah[mt][1] = Qh[(r + 8)*PAD + kc + t    ];
            ah[mt][2] = Qh[ r     *PAD + kc + t + 4];
            ah[mt][3] = Qh[(r + 8)*PAD + kc + t + 4];
            al[mt][0] = Ql[ r     *PAD + kc + t    ];
            al[mt][1] = Ql[(r + 8)*PAD + kc + t    ];
            al[mt][2] = Ql[ r     *PAD + kc + t + 4];
            al[mt][3] = Ql[(r + 8)*PAD + kc + t + 4];
        }
#pragma unroll
        for (int nt = 0; nt < 4; nt++) {
            int n = wx*32 + nt*8 + g;
            unsigned bh[2], bl[2];
            bh[0] = Kh[n*PAD + kc + t];
            bh[1] = Kh[n*PAD + kc + t + 4];
            bl[0] = Kl[n*PAD + kc + t];
            bl[1] = Kl[n*PAD + kc + t + 4];
#pragma unroll
            for (int mt = 0; mt < 2; mt++) {
                mma_tf32(c[mt][nt], ah[mt], bh);
                mma_tf32(c[mt][nt], ah[mt], bl);
                mma_tf32(c[mt][nt], al[mt], bh);
            }
        }
    }

    __syncthreads();             // tile smem no longer needed -> reuse for stats
    float* red = (float*)su;     // [3][128 rows][8 slots]

    const float sc = 0.03125f;   // 1/sqrt(1024)
    float rsum_[4] = {}, rsq_[4] = {};
    float rmx_[4] = {-1e30f, -1e30f, -1e30f, -1e30f};
#pragma unroll
    for (int mt = 0; mt < 2; mt++) {
#pragma unroll
        for (int nt = 0; nt < 4; nt++) {
            int rrow = i0 + wy*32 + mt*16 + g;
            int ccol = j0 + wx*32 + nt*8 + 2*t;
            float v0 = c[mt][nt][0]*sc, v1 = c[mt][nt][1]*sc;
            float v2 = c[mt][nt][2]*sc, v3 = c[mt][nt][3]*sc;
            *(float2*)(g_scores + ((size_t)b*SS + rrow    )*SS + ccol) = make_float2(v0, v1);
            *(float2*)(g_scores + ((size_t)b*SS + rrow + 8)*SS + ccol) = make_float2(v2, v3);
            int p0 = mt*2, p1 = mt*2 + 1;
            rsum_[p0] += v0 + v1;  rsq_[p0] += v0*v0 + v1*v1;
            rmx_[p0] = fmaxf(rmx_[p0], fmaxf(v0, v1));
            rsum_[p1] += v2 + v3;  rsq_[p1] += v2*v2 + v3*v3;
            rmx_[p1] = fmaxf(rmx_[p1], fmaxf(v2, v3));
        }
    }
    const int slot = wx*4 + t;
#pragma unroll
    for (int p = 0; p < 4; p++) {
        int row = wy*32 + p*8 + g;
        red[(0*128 + row)*8 + slot] = rsum_[p];
        red[(1*128 + row)*8 + slot] = rsq_[p];
        red[(2*128 + row)*8 + slot] = rmx_[p];
    }
    __syncthreads();
    if (tid < 128) {
        float S = 0.f, Q = 0.f, M = -1e30f;
#pragma unroll
        for (int s = 0; s < 8; s++) {
            S += red[(0*128 + tid)*8 + s];
            Q += red[(1*128 + tid)*8 + s];
            M  = fmaxf(M, red[(2*128 + tid)*8 + s]);
        }
        int rg = b*SS + i0 + tid;
        g_ssum[blockIdx.x*RR + rg] = S;
        g_ssq [blockIdx.x*RR + rg] = Q;
        g_smx [blockIdx.x*RR + rg] = M;
    }
}

// ---------------------------------------------------------------------------
// K3: finalize row stats: rstd, a
// ---------------------------------------------------------------------------
__global__ void __launch_bounds__(256) stats_finalize() {
    int r = blockIdx.x * 256 + threadIdx.x;    // < RR
    float S = 0.f, Q = 0.f, M = -1e30f;
#pragma unroll
    for (int jt = 0; jt < NJT; jt++) {
        S += g_ssum[jt*RR + r];
        Q += g_ssq [jt*RR + r];
        M  = fmaxf(M, g_smx[jt*RR + r]);
    }
    float mean = S * (1.f/(float)SS);
    float var  = (Q - S*mean) * (1.f/(float)(SS-1));   // ddof=1
    float rstd = 1.f / (sqrtf(fmaxf(var, 0.f)) + 1e-8f);
    g_rstd[r] = rstd;
    g_a[r]    = mean*rstd + (M - mean)*rstd;
}

// ---------------------------------------------------------------------------
// K4: headp[js] = exp(ln-softmax numer) @ V over j-range [js*512, +512)
//     block: 32 rows x 512 cols x D=64; jt step 128; grid (64, 4, 4)
// ---------------------------------------------------------------------------
__global__ void __launch_bounds__(256) pv_mma() {
    extern __shared__ unsigned pvsm[];
    unsigned* Ps = pvsm;               // [32][PPAD]
    unsigned* Vs = pvsm + 32*PPAD;     // [128][VPAD]
    __shared__ float s_rstd[32], s_a[32], s_esum[32];

    const int b  = blockIdx.y;
    const int js = blockIdx.z;
    const int i0 = blockIdx.x * 32;
    const int rowg0 = b*SS + i0;
    const int jbase = js * (SS/NSPLIT);
    const int tid  = threadIdx.x;
    const int warp = tid >> 5, lane = tid & 31;
    const int g = lane >> 2, t = lane & 3;
    const int wy = warp >> 2, wx = warp & 3;
    const int myrow = tid >> 3;
    const int lane8 = tid & 7;
    const float* srow = g_scores + ((size_t)rowg0 + myrow)*SS;

    if (tid < 32) { s_rstd[tid] = g_rstd[rowg0 + tid]; s_a[tid] = g_a[rowg0 + tid]; }
    __syncthreads();
    const float rstd = s_rstd[myrow], aa = s_a[myrow];

    float acc[2][4] = {};
    float esum = 0.f;
    for (int jt = jbase; jt < jbase + SS/NSPLIT; jt += 128) {
#pragma unroll
        for (int q = 0; q < 4; q++) {
            int c4 = (lane8 + 8*q)*4;
            float4 s = *(const float4*)(srow + jt + c4);
            float e0 = __expf(fmaf(s.x, rstd, -aa));
            float e1 = __expf(fmaf(s.y, rstd, -aa));
            float e2 = __expf(fmaf(s.z, rstd, -aa));
            float e3 = __expf(fmaf(s.w, rstd, -aa));
            esum += (e0 + e1) + (e2 + e3);
            *(uint4*)&Ps[myrow*PPAD + c4] = make_uint4(f2tf(e0), f2tf(e1), f2tf(e2), f2tf(e3));
        }
#pragma unroll
        for (int p = 0; p < 8; p++) {
            int idx = p*256 + tid;
            int jl = idx >> 4, n4 = (idx & 15) * 4;
            float4 v = *(const float4*)(g_v + (size_t)(b*SS + jt + jl)*DD + n4);
            *(uint4*)&Vs[jl*VPAD + n4] = make_uint4(f2tf(v.x), f2tf(v.y), f2tf(v.z), f2tf(v.w));
        }
        __syncthreads();
#pragma unroll
        for (int k8 = 0; k8 < 16; k8++) {
            const int kc = k8*8;
            unsigned a[4];
            int r = wy*16 + g;
            a[0] = Ps[ r     *PPAD + kc + t    ];
            a[1] = Ps[(r + 8)*PPAD + kc + t    ];
            a[2] = Ps[ r     *PPAD + kc + t + 4];
            a[3] = Ps[(r + 8)*PPAD + kc + t + 4];
#pragma unroll
            for (int nt = 0; nt < 2; nt++) {
                int n = wx*16 + nt*8 + g;
                unsigned bb[2];
                bb[0] = Vs[(kc + t    )*VPAD + n];
                bb[1] = Vs[(kc + t + 4)*VPAD + n];
                mma_tf32(acc[nt], a, bb);
            }
        }
        __syncthreads();
    }

#pragma unroll
    for (int o = 4; o; o >>= 1) esum += __shfl_xor_sync(~0u, esum, o);
    if (lane8 == 0) s_esum[myrow] = esum;
    __syncthreads();
    if (tid < 32) g_esump[js*RR + rowg0 + tid] = s_esum[tid];

    float* Hp = g_headp + (size_t)js*RR*DD;
    int r0 = wy*16 + g, r1 = r0 + 8;
#pragma unroll
    for (int nt = 0; nt < 2; nt++) {
        int col = wx*16 + nt*8 + 2*t;
        *(float2*)(Hp + (size_t)(rowg0 + r0)*DD + col) = make_float2(acc[nt][0], acc[nt][1]);
        *(float2*)(Hp + (size_t)(rowg0 + r1)*DD + col) = make_float2(acc[nt][2], acc[nt][3]);
    }
}

// ---------------------------------------------------------------------------
// K5: out = (sum headp / sum esump) @ W_eff + bout via 3xTF32 mma
// ---------------------------------------------------------------------------
__global__ void __launch_bounds__(256) out_mma(const float* __restrict__ bout,
                                               float* __restrict__ out) {
    extern __shared__ unsigned om[];
    unsigned* Hh = om;
    unsigned* Hl = om + 64*PAD;
    unsigned* Wh = om + 2*64*PAD;
    unsigned* Wl = om + 2*64*PAD + 64*WPAD;
    __shared__ float s_recip[64];

    const int mbase = blockIdx.x * 64;
    const int nbase = blockIdx.y * 128;
    const int tid  = threadIdx.x;
    const int warp = tid >> 5, lane = tid & 31;
    const int g = lane >> 2, t = lane & 3;
    const int wy = warp >> 1, wx = warp & 1;

    if (tid < 64) {
        int rg = mbase + tid;
        float e = g_esump[rg] + g_esump[RR + rg] + g_esump[2*RR + rg] + g_esump[3*RR + rg];
        s_recip[tid] = 1.f / e;
    }
    __syncthreads();

#pragma unroll
    for (int p = 0; p < 4; p++) {
        int idx = p*256 + tid;
        int row = idx >> 4, c4 = (idx & 15) * 4;
        size_t off = (size_t)(mbase + row)*DD + c4;
        float4 a0 = *(const float4*)(g_headp + off);
        float4 a1 = *(const float4*)(g_headp + (size_t)RR*DD + off);
        float4 a2 = *(const float4*)(g_headp + (size_t)2*RR*DD + off);
        float4 a3 = *(const float4*)(g_headp + (size_t)3*RR*DD + off);
        float rc = s_recip[row];
        float4 h4 = make_float4(((a0.x+a1.x)+(a2.x+a3.x))*rc, ((a0.y+a1.y)+(a2.y+a3.y))*rc,
                                ((a0.z+a1.z)+(a2.z+a3.z))*rc, ((a0.w+a1.w)+(a2.w+a3.w))*rc);
        uint4 h, l;
        hilo(h4.x, h.x, l.x); hilo(h4.y, h.y, l.y);
        hilo(h4.z, h.z, l.z); hilo(h4.w, h.w, l.w);
        *(uint4*)&Hh[row*PAD + c4] = h;
        *(uint4*)&Hl[row*PAD + c4] = l;
    }
#pragma unroll
    for (int p = 0; p < 8; p++) {
        int idx = p*256 + tid;
        int k = idx >> 5, n4 = (idx & 31) * 4;
        float4 w4 = *(const float4*)(g_weff + (size_t)k*HID + nbase + n4);
        uint4 h, l;
        hilo(w4.x, h.x, l.x); hilo(w4.y, h.y, l.y);
        hilo(w4.z, h.z, l.z); hilo(w4.w, h.w, l.w);
        *(uint4*)&Wh[k*WPAD + n4] = h;
        *(uint4*)&Wl[k*WPAD + n4] = l;
    }
    __syncthreads();

    float acc[8][4] = {};
#pragma unroll
    for (int k8 = 0; k8 < 8; k8++) {
        const int kc = k8*8;
        unsigned ah[4], al[4];
        int r = wy*16 + g;
        ah[0] = Hh[ r     *PAD + kc + t    ];
        ah[1] = Hh[(r + 8)*PAD + kc + t    ];
        ah[2] = Hh[ r     *PAD + kc + t + 4];
        ah[3] = Hh[(r + 8)*PAD + kc + t + 4];
        al[0] = Hl[ r     *PAD + kc + t    ];
        al[1] = Hl[(r + 8)*PAD + kc + t    ];
        al[2] = Hl[ r     *PAD + kc + t + 4];
        al[3] = Hl[(r + 8)*PAD + kc + t + 4];
#pragma unroll
        for (int nt = 0; nt < 8; nt++) {
            int n = wx*64 + nt*8 + g;
            unsigned bh[2], bl[2];
            bh[0] = Wh[(kc + t    )*WPAD + n];
            bh[1] = Wh[(kc + t + 4)*WPAD + n];
            bl[0] = Wl[(kc + t    )*WPAD + n];
            bl[1] = Wl[(kc + t + 4)*WPAD + n];
            mma_tf32(acc[nt], ah, bh);
            mma_tf32(acc[nt], ah, bl);
            mma_tf32(acc[nt], al, bh);
        }
    }

    int r0 = mbase + wy*16 + g, r1 = r0 + 8;
#pragma unroll
    for (int nt = 0; nt < 8; nt++) {
        int col = nbase + wx*64 + nt*8 + 2*t;
        float b0 = bout[col], b1 = bout[col+1];
        *(float2*)(out + (size_t)r0*HID + col) = make_float2(acc[nt][0]+b0, acc[nt][1]+b1);
        *(float2*)(out + (size_t)r1*HID + col) = make_float2(acc[nt][2]+b0, acc[nt][3]+b1);
    }
}

// ---------------------------------------------------------------------------
extern "C" void kernel_launch(void* const* d_in, const int* in_sizes, int n_in,
                              void* d_out, int out_size) {
    (void)in_sizes; (void)n_in; (void)out_size;
    const float* query = (const float*)d_in[0];
    const float* key   = (const float*)d_in[1];
    const float* value = (const float*)d_in[2];
    // d_in[3] mask: adding -1e-32 is a numeric no-op in fp32 -> skipped
    const float* Wq   = (const float*)d_in[4];
    const float* bq   = (const float*)d_in[5];
    const float* Wk   = (const float*)d_in[6];
    const float* bk   = (const float*)d_in[7];
    const float* Wv   = (const float*)d_in[8];
    const float* bv   = (const float*)d_in[9];
    const float* Wout = (const float*)d_in[10];
    const float* bout = (const float*)d_in[11];
    // d_in[12] seq_mask == 0 -> no causal mask
    float* out = (float*)d_out;

    const int proj_smem   = (2*128*XPAD + 2*32*VPAD) * 4;        // 55296 B
    const int scores_smem = (2*128*PAD + 2*64*PAD) * 4;          // 104448 B
    const int pv_smem     = (32*PPAD + 128*VPAD) * 4;            // 53760 B
    const int out_smem    = (2*64*PAD + 2*64*WPAD) * 4;          // 104448 B
    cudaFuncSetAttribute(proj_mma,   cudaFuncAttributeMaxDynamicSharedMemorySize, proj_smem);
    cudaFuncSetAttribute(scores_mma, cudaFuncAttributeMaxDynamicSharedMemorySize, scores_smem);
    cudaFuncSetAttribute(pv_mma,     cudaFuncAttributeMaxDynamicSharedMemorySize, pv_smem);
    cudaFuncSetAttribute(out_mma,    cudaFuncAttributeMaxDynamicSharedMemorySize, out_smem);

    weff_kernel<<<256, 256>>>(Wout);
    proj_mma<<<dim3(64, 3), 256, proj_smem>>>(query, key, value, Wq, Wk, Wv, bq, bk, bv);
    scores_mma<<<dim3(NJT, 16, 4), 256, scores_smem>>>();
    stats_finalize<<<RR/256, 256>>>();
    pv_mma<<<dim3(64, 4, NSPLIT), 256, pv_smem>>>();
    out_mma<<<dim3(128, 8), 256, out_smem>>>(bout, out);
}

// round 6
// speedup vs baseline: 1.6262x; 1.3345x over previous
#include <cuda_runtime.h>
#include <cuda_bf16.h>
#include <cuda_fp16.h>
#include <math.h>

#define BB 4
#define SS 2048
#define HID 1024
#define DD 64
#define RR (BB*SS)   // 8192 rows
#define NJT 32       // 64-wide j-tiles in scores
#define NSPLIT 4     // pv j-splits
// u32 smem row strides (pads chosen for conflict-free mma fragment loads)
#define AP 36        // 64-K A/B tiles (32 u32 + 4): bank = 4*row + t
#define PP 68        // 128-K P tile (64 u32 + 4): bank = 4*row + t
#define VP 72        // V tile [jpair][d] (64 + 8): bank = 8*row + n

// ---- scratch (static device arrays; no allocation) ----
static __device__ float  g_q[RR*DD];
static __device__ float  g_k[RR*DD];
static __device__ float  g_v[RR*DD];
static __device__ __half g_scores[(size_t)RR*SS];      // 33.5 MB
static __device__ unsigned g_wth[3*64*512], g_wtl[3*64*512];     // W^T packed bf16 pairs
static __device__ unsigned g_wefft_h[HID*32], g_wefft_l[HID*32]; // W_eff^T packed
static __device__ float  g_ssum[NJT*RR];
static __device__ float  g_ssq [NJT*RR];
static __device__ float  g_smx [NJT*RR];
static __device__ float  g_rstd[RR];
static __device__ float  g_a[RR];
static __device__ float  g_esump[NSPLIT*RR];
static __device__ float  g_headp[(size_t)NSPLIT*RR*DD];

// ---------------------------------------------------------------------------
// helpers: bf16 hi/lo split + mma m16n8k16 bf16
// ---------------------------------------------------------------------------
__device__ __forceinline__ void split2(float x0, float x1, unsigned& h, unsigned& l) {
    __nv_bfloat16 h0 = __float2bfloat16_rn(x0);
    __nv_bfloat16 h1 = __float2bfloat16_rn(x1);
    __nv_bfloat16 l0 = __float2bfloat16_rn(x0 - __bfloat162float(h0));
    __nv_bfloat16 l1 = __float2bfloat16_rn(x1 - __bfloat162float(h1));
    h = (unsigned)__bfloat16_as_ushort(h0) | ((unsigned)__bfloat16_as_ushort(h1) << 16);
    l = (unsigned)__bfloat16_as_ushort(l0) | ((unsigned)__bfloat16_as_ushort(l1) << 16);
}
__device__ __forceinline__ void mma_bf16(float* c, const unsigned* a, const unsigned* b) {
    asm volatile(
        "mma.sync.aligned.m16n8k16.row.col.f32.bf16.bf16.f32 "
        "{%0,%1,%2,%3}, {%4,%5,%6,%7}, {%8,%9}, {%0,%1,%2,%3};"
        : "+f"(c[0]), "+f"(c[1]), "+f"(c[2]), "+f"(c[3])
        : "r"(a[0]), "r"(a[1]), "r"(a[2]), "r"(a[3]), "r"(b[0]), "r"(b[1]));
}
// 3-term split product: hi*hi + hi*lo + lo*hi
__device__ __forceinline__ void mma3(float* c, const unsigned* ah, const unsigned* al,
                                     const unsigned* bh, const unsigned* bl) {
    mma_bf16(c, ah, bh);
    mma_bf16(c, ah, bl);
    mma_bf16(c, al, bh);
}

// ---------------------------------------------------------------------------
// P0a: transpose+pack Wq/Wk/Wv -> g_wth/g_wtl [which][n=64][kpair=512]
// ---------------------------------------------------------------------------
__global__ void wqkvt_prep(const float* __restrict__ Wq, const float* __restrict__ Wk,
                           const float* __restrict__ Wv) {
    const int which = blockIdx.y;
    const float* W = which == 0 ? Wq : which == 1 ? Wk : Wv;
    int kp = blockIdx.x * 4 + (threadIdx.x >> 6);
    int n  = threadIdx.x & 63;
    float w0 = W[(size_t)(2*kp)*DD + n];
    float w1 = W[(size_t)(2*kp + 1)*DD + n];
    unsigned h, l; split2(w0, w1, h, l);
    g_wth[(which*64 + n)*512 + kp] = h;
    g_wtl[(which*64 + n)*512 + kp] = l;
}

// ---------------------------------------------------------------------------
// P0b: W_eff^T packed: g_wefft[n=1024][kpair=32], W_eff[r][c] = sum_h Wout[h*64+r][c]
// ---------------------------------------------------------------------------
__global__ void wefft_prep(const float* __restrict__ Wout) {
    int kp = blockIdx.y;                              // 0..31
    int n  = blockIdx.x * 256 + threadIdx.x;          // 0..1023
    float s0 = 0.f, s1 = 0.f;
#pragma unroll
    for (int h = 0; h < 16; h++) {
        s0 += Wout[(size_t)(h*64 + 2*kp    )*HID + n];
        s1 += Wout[(size_t)(h*64 + 2*kp + 1)*HID + n];
    }
    unsigned h, l; split2(s0, s1, h, l);
    g_wefft_h[n*32 + kp] = h;
    g_wefft_l[n*32 + kp] = l;
}

// ---------------------------------------------------------------------------
// K1: Q/K/V projections, bf16 3-term: [8192,1024]@[1024,64]+b
//     block 128m x 64n, K chunks of 64; 8 warps (4x2), warp 32x32
// ---------------------------------------------------------------------------
__global__ void __launch_bounds__(256) proj_mma(
    const float* __restrict__ xq, const float* __restrict__ xk, const float* __restrict__ xv,
    const float* __restrict__ bq, const float* __restrict__ bk, const float* __restrict__ bv)
{
    extern __shared__ unsigned sm[];
    unsigned* Xh = sm;                        // [128][AP]
    unsigned* Xl = sm + 128*AP;
    unsigned* Wh = sm + 2*128*AP;             // [64][AP]
    unsigned* Wl = sm + 2*128*AP + 64*AP;

    const int which = blockIdx.y;
    const float* X    = which == 0 ? xq : which == 1 ? xk : xv;
    const float* bias = which == 0 ? bq : which == 1 ? bk : bv;
    float*       O    = which == 0 ? g_q : which == 1 ? g_k : g_v;

    const int mbase = blockIdx.x * 128;
    const int tid  = threadIdx.x;
    const int warp = tid >> 5, lane = tid & 31;
    const int g = lane >> 2, t = lane & 3;
    const int wy = warp >> 1, wx = warp & 1;

    float acc[2][4][4] = {};

    for (int kk = 0; kk < HID; kk += 64) {
#pragma unroll
        for (int p = 0; p < 8; p++) {          // X tile 128x64 -> hi/lo pairs
            int idx = p*256 + tid;
            int row = idx >> 4, f4 = idx & 15;
            float4 v = *(const float4*)(X + (size_t)(mbase + row)*HID + kk + f4*4);
            unsigned h0, l0, h1, l1;
            split2(v.x, v.y, h0, l0); split2(v.z, v.w, h1, l1);
            *(uint2*)&Xh[row*AP + f4*2] = make_uint2(h0, h1);
            *(uint2*)&Xl[row*AP + f4*2] = make_uint2(l0, l1);
        }
#pragma unroll
        for (int p = 0; p < 2; p++) {          // W stage from packed-transposed gmem
            int idx = p*256 + tid;
            int n = idx >> 3, k4 = (idx & 7) * 4;
            *(uint4*)&Wh[n*AP + k4] = *(const uint4*)&g_wth[(which*64 + n)*512 + kk/2 + k4];
            *(uint4*)&Wl[n*AP + k4] = *(const uint4*)&g_wtl[(which*64 + n)*512 + kk/2 + k4];
        }
        __syncthreads();
#pragma unroll
        for (int c = 0; c < 4; c++) {
            const int kc = c*8;
            unsigned ah[2][4], al[2][4];
#pragma unroll
            for (int mt = 0; mt < 2; mt++) {
                int r = wy*32 + mt*16 + g;
                ah[mt][0] = Xh[ r     *AP + kc + t    ];
                ah[mt][1] = Xh[(r + 8)*AP + kc + t    ];
                ah[mt][2] = Xh[ r     *AP + kc + t + 4];
                ah[mt][3] = Xh[(r + 8)*AP + kc + t + 4];
                al[mt][0] = Xl[ r     *AP + kc + t    ];
                al[mt][1] = Xl[(r + 8)*AP + kc + t    ];
                al[mt][2] = Xl[ r     *AP + kc + t + 4];
                al[mt][3] = Xl[(r + 8)*AP + kc + t + 4];
            }
#pragma unroll
            for (int nt = 0; nt < 4; nt++) {
                int n = wx*32 + nt*8 + g;
                unsigned bh[2], bl[2];
                bh[0] = Wh[n*AP + kc + t];     bh[1] = Wh[n*AP + kc + t + 4];
                bl[0] = Wl[n*AP + kc + t];     bl[1] = Wl[n*AP + kc + t + 4];
#pragma unroll
                for (int mt = 0; mt < 2; mt++) mma3(acc[mt][nt], ah[mt], al[mt], bh, bl);
            }
        }
        __syncthreads();
    }
#pragma unroll
    for (int mt = 0; mt < 2; mt++) {
#pragma unroll
        for (int nt = 0; nt < 4; nt++) {
            int r = mbase + wy*32 + mt*16 + g;
            int col = wx*32 + nt*8 + 2*t;
            float b0 = bias[col], b1 = bias[col+1];
            *(float2*)(O + (size_t)r*DD + col)       = make_float2(acc[mt][nt][0]+b0, acc[mt][nt][1]+b1);
            *(float2*)(O + (size_t)(r + 8)*DD + col) = make_float2(acc[mt][nt][2]+b0, acc[mt][nt][3]+b1);
        }
    }
}

// ---------------------------------------------------------------------------
// K2: scores = (Q K^T)/32 bf16 3-term + fused row-stat partials; fp16 output
//     block 128x64 tile, K=64 single shot
// ---------------------------------------------------------------------------
__global__ void __launch_bounds__(256) scores_mma() {
    extern __shared__ unsigned su[];
    unsigned* Qh = su;                        // [128][AP]
    unsigned* Ql = su + 128*AP;
    unsigned* Kh = su + 2*128*AP;             // [64][AP]
    unsigned* Kl = su + 2*128*AP + 64*AP;

    const int b  = blockIdx.z;
    const int i0 = blockIdx.y * 128, j0 = blockIdx.x * 64;
    const int tid  = threadIdx.x;
    const int warp = tid >> 5, lane = tid & 31;
    const int g = lane >> 2, t = lane & 3;
    const int wy = warp >> 1, wx = warp & 1;

#pragma unroll
    for (int p = 0; p < 8; p++) {
        int idx = p*256 + tid;
        int row = idx >> 4, f4 = idx & 15;
        float4 q = *(const float4*)(g_q + (size_t)(b*SS + i0 + row)*DD + f4*4);
        unsigned h0, l0, h1, l1;
        split2(q.x, q.y, h0, l0); split2(q.z, q.w, h1, l1);
        *(uint2*)&Qh[row*AP + f4*2] = make_uint2(h0, h1);
        *(uint2*)&Ql[row*AP + f4*2] = make_uint2(l0, l1);
    }
#pragma unroll
    for (int p = 0; p < 4; p++) {
        int idx = p*256 + tid;
        int row = idx >> 4, f4 = idx & 15;
        float4 k = *(const float4*)(g_k + (size_t)(b*SS + j0 + row)*DD + f4*4);
        unsigned h0, l0, h1, l1;
        split2(k.x, k.y, h0, l0); split2(k.z, k.w, h1, l1);
        *(uint2*)&Kh[row*AP + f4*2] = make_uint2(h0, h1);
        *(uint2*)&Kl[row*AP + f4*2] = make_uint2(l0, l1);
    }
    __syncthreads();

    float c[2][4][4] = {};
#pragma unroll
    for (int kc8 = 0; kc8 < 4; kc8++) {
        const int kc = kc8*8;
        unsigned ah[2][4], al[2][4];
#pragma unroll
        for (int mt = 0; mt < 2; mt++) {
            int r = wy*32 + mt*16 + g;
            ah[mt][0] = Qh[ r     *AP + kc + t    ];
            ah[mt][1] = Qh[(r + 8)*AP + kc + t    ];
            ah[mt][2] = Qh[ r     *AP + kc + t + 4];
            ah[mt][3] = Qh[(r + 8)*AP + kc + t + 4];
            al[mt][0] = Ql[ r     *AP + kc + t    ];
            al[mt][1] = Ql[(r + 8)*AP + kc + t    ];
            al[mt][2] = Ql[ r     *AP + kc + t + 4];
            al[mt][3] = Ql[(r + 8)*AP + kc + t + 4];
        }
#pragma unroll
        for (int nt = 0; nt < 4; nt++) {
            int n = wx*32 + nt*8 + g;
            unsigned bh[2], bl[2];
            bh[0] = Kh[n*AP + kc + t];     bh[1] = Kh[n*AP + kc + t + 4];
            bl[0] = Kl[n*AP + kc + t];     bl[1] = Kl[n*AP + kc + t + 4];
#pragma unroll
            for (int mt = 0; mt < 2; mt++) mma3(c[mt][nt], ah[mt], al[mt], bh, bl);
        }
    }

    __syncthreads();             // reuse tile smem for stats reduction
    float* red = (float*)su;     // [3][128][8]

    const float sc = 0.03125f;   // 1/sqrt(1024)
    float rsum_[4] = {}, rsq_[4] = {};
    float rmx_[4] = {-1e30f, -1e30f, -1e30f, -1e30f};
#pragma unroll
    for (int mt = 0; mt < 2; mt++) {
#pragma unroll
        for (int nt = 0; nt < 4; nt++) {
            int rrow = i0 + wy*32 + mt*16 + g;
            int ccol = j0 + wx*32 + nt*8 + 2*t;
            float v0 = c[mt][nt][0]*sc, v1 = c[mt][nt][1]*sc;
            float v2 = c[mt][nt][2]*sc, v3 = c[mt][nt][3]*sc;
            *(__half2*)&g_scores[((size_t)b*SS + rrow    )*SS + ccol] = __floats2half2_rn(v0, v1);
            *(__half2*)&g_scores[((size_t)b*SS + rrow + 8)*SS + ccol] = __floats2half2_rn(v2, v3);
            int p0 = mt*2, p1 = mt*2 + 1;
            rsum_[p0] += v0 + v1;  rsq_[p0] += v0*v0 + v1*v1;
            rmx_[p0] = fmaxf(rmx_[p0], fmaxf(v0, v1));
            rsum_[p1] += v2 + v3;  rsq_[p1] += v2*v2 + v3*v3;
            rmx_[p1] = fmaxf(rmx_[p1], fmaxf(v2, v3));
        }
    }
    const int slot = wx*4 + t;
#pragma unroll
    for (int p = 0; p < 4; p++) {
        int row = wy*32 + p*8 + g;
        red[(0*128 + row)*8 + slot] = rsum_[p];
        red[(1*128 + row)*8 + slot] = rsq_[p];
        red[(2*128 + row)*8 + slot] = rmx_[p];
    }
    __syncthreads();
    if (tid < 128) {
        float S = 0.f, Q = 0.f, M = -1e30f;
#pragma unroll
        for (int s = 0; s < 8; s++) {
            S += red[(0*128 + tid)*8 + s];
            Q += red[(1*128 + tid)*8 + s];
            M  = fmaxf(M, red[(2*128 + tid)*8 + s]);
        }
        int rg = b*SS + i0 + tid;
        g_ssum[blockIdx.x*RR + rg] = S;
        g_ssq [blockIdx.x*RR + rg] = Q;
        g_smx [blockIdx.x*RR + rg] = M;
    }
}

// ---------------------------------------------------------------------------
// K3: finalize row stats
// ---------------------------------------------------------------------------
__global__ void __launch_bounds__(256) stats_finalize() {
    int r = blockIdx.x * 256 + threadIdx.x;
    float S = 0.f, Q = 0.f, M = -1e30f;
#pragma unroll
    for (int jt = 0; jt < NJT; jt++) {
        S += g_ssum[jt*RR + r];
        Q += g_ssq [jt*RR + r];
        M  = fmaxf(M, g_smx[jt*RR + r]);
    }
    float mean = S * (1.f/(float)SS);
    float var  = (Q - S*mean) * (1.f/(float)(SS-1));   // ddof=1
    float rstd = 1.f / (sqrtf(fmaxf(var, 0.f)) + 1e-8f);
    g_rstd[r] = rstd;
    g_a[r]    = mean*rstd + (M - mean)*rstd;
}

// ---------------------------------------------------------------------------
// K4: headp[js] = exp(ln-softmax numer) @ V over 512-wide j range, bf16 3-term
//     block 32 rows, jt step 128; 8 warps (2x4), warp 16x16
// ---------------------------------------------------------------------------
__global__ void __launch_bounds__(256) pv_mma() {
    extern __shared__ unsigned pvsm[];
    unsigned* Psh = pvsm;                     // [32][PP]
    unsigned* Psl = pvsm + 32*PP;
    unsigned* Vsh = pvsm + 2*32*PP;           // [64][VP] (jpair rows)
    unsigned* Vsl = pvsm + 2*32*PP + 64*VP;
    __shared__ float s_rstd[32], s_a[32], s_esum[32];

    const int b  = blockIdx.y;
    const int js = blockIdx.z;
    const int i0 = blockIdx.x * 32;
    const int rowg0 = b*SS + i0;
    const int jbase = js * (SS/NSPLIT);
    const int tid  = threadIdx.x;
    const int warp = tid >> 5, lane = tid & 31;
    const int g = lane >> 2, t = lane & 3;
    const int wy = warp >> 2, wx = warp & 3;
    const int myrow = tid >> 3;
    const int lane8 = tid & 7;
    const __half* srow = g_scores + ((size_t)rowg0 + myrow)*SS;

    if (tid < 32) { s_rstd[tid] = g_rstd[rowg0 + tid]; s_a[tid] = g_a[rowg0 + tid]; }
    __syncthreads();
    const float rstd = s_rstd[myrow], aa = s_a[myrow];

    float acc[2][4] = {};
    float esum = 0.f;
    for (int jt = jbase; jt < jbase + SS/NSPLIT; jt += 128) {
#pragma unroll
        for (int q = 0; q < 4; q++) {          // exp + split P (pairs along j)
            int c4 = (lane8 + 8*q)*4;          // j offset, multiple of 4
            uint2 raw = *(const uint2*)(srow + jt + c4);
            float2 f01 = __half22float2(*(__half2*)&raw.x);
            float2 f23 = __half22float2(*(__half2*)&raw.y);
            float e0 = __expf(fmaf(f01.x, rstd, -aa));
            float e1 = __expf(fmaf(f01.y, rstd, -aa));
            float e2 = __expf(fmaf(f23.x, rstd, -aa));
            float e3 = __expf(fmaf(f23.y, rstd, -aa));
            esum += (e0 + e1) + (e2 + e3);
            unsigned h0, l0, h1, l1;
            split2(e0, e1, h0, l0); split2(e2, e3, h1, l1);
            *(uint2*)&Psh[myrow*PP + c4/2] = make_uint2(h0, h1);
            *(uint2*)&Psl[myrow*PP + c4/2] = make_uint2(l0, l1);
        }
#pragma unroll
        for (int p = 0; p < 4; p++) {          // V tile: pack pairs along j
            int idx = p*256 + tid;
            int jp = idx >> 4, d4 = (idx & 15) * 4;
            float4 v0 = *(const float4*)(g_v + (size_t)(b*SS + jt + 2*jp    )*DD + d4);
            float4 v1 = *(const float4*)(g_v + (size_t)(b*SS + jt + 2*jp + 1)*DD + d4);
            unsigned h0,l0,h1,l1,h2,l2,h3,l3;
            split2(v0.x, v1.x, h0, l0); split2(v0.y, v1.y, h1, l1);
            split2(v0.z, v1.z, h2, l2); split2(v0.w, v1.w, h3, l3);
            *(uint4*)&Vsh[jp*VP + d4] = make_uint4(h0, h1, h2, h3);
            *(uint4*)&Vsl[jp*VP + d4] = make_uint4(l0, l1, l2, l3);
        }
        __syncthreads();
#pragma unroll
        for (int c = 0; c < 8; c++) {          // 128 j = 8 k16 chunks
            const int kc = c*8;                // u32 (jpair) offset
            unsigned ah[4], al[4];
            int r = wy*16 + g;
            ah[0] = Psh[ r     *PP + kc + t    ];
            ah[1] = Psh[(r + 8)*PP + kc + t    ];
            ah[2] = Psh[ r     *PP + kc + t + 4];
            ah[3] = Psh[(r + 8)*PP + kc + t + 4];
            al[0] = Psl[ r     *PP + kc + t    ];
            al[1] = Psl[(r + 8)*PP + kc + t    ];
            al[2] = Psl[ r     *PP + kc + t + 4];
            al[3] = Psl[(r + 8)*PP + kc + t + 4];
#pragma unroll
            for (int nt = 0; nt < 2; nt++) {
                int n = wx*16 + nt*8 + g;
                unsigned bh[2], bl[2];
                bh[0] = Vsh[(kc + t    )*VP + n];
                bh[1] = Vsh[(kc + t + 4)*VP + n];
                bl[0] = Vsl[(kc + t    )*VP + n];
                bl[1] = Vsl[(kc + t + 4)*VP + n];
                mma3(acc[nt], ah, al, bh, bl);
            }
        }
        __syncthreads();
    }

#pragma unroll
    for (int o = 4; o; o >>= 1) esum += __shfl_xor_sync(~0u, esum, o);
    if (lane8 == 0) s_esum[myrow] = esum;
    __syncthreads();
    if (tid < 32) g_esump[js*RR + rowg0 + tid] = s_esum[tid];

    float* Hp = g_headp + (size_t)js*RR*DD;
    int r0 = wy*16 + g, r1 = r0 + 8;
#pragma unroll
    for (int nt = 0; nt < 2; nt++) {
        int col = wx*16 + nt*8 + 2*t;
        *(float2*)(Hp + (size_t)(rowg0 + r0)*DD + col) = make_float2(acc[nt][0], acc[nt][1]);
        *(float2*)(Hp + (size_t)(rowg0 + r1)*DD + col) = make_float2(acc[nt][2], acc[nt][3]);
    }
}

// ---------------------------------------------------------------------------
// K5: out = (sum headp / sum esump) @ W_eff + bout, bf16 3-term
//     block 64m x 128n, K=64; 8 warps (4x2), warp 16x64
// ---------------------------------------------------------------------------
__global__ void __launch_bounds__(256) out_mma(const float* __restrict__ bout,
                                               float* __restrict__ out) {
    extern __shared__ unsigned om[];
    unsigned* Hh = om;                        // [64][AP]
    unsigned* Hl = om + 64*AP;
    unsigned* Wh = om + 2*64*AP;              // [128][AP]
    unsigned* Wl = om + 2*64*AP + 128*AP;
    __shared__ float s_recip[64];

    const int mbase = blockIdx.x * 64;
    const int nbase = blockIdx.y * 128;
    const int tid  = threadIdx.x;
    const int warp = tid >> 5, lane = tid & 31;
    const int g = lane >> 2, t = lane & 3;
    const int wy = warp >> 1, wx = warp & 1;

    if (tid < 64) {
        int rg = mbase + tid;
        float e = g_esump[rg] + g_esump[RR + rg] + g_esump[2*RR + rg] + g_esump[3*RR + rg];
        s_recip[tid] = 1.f / e;
    }
    __syncthreads();

#pragma unroll
    for (int p = 0; p < 4; p++) {              // H = sum of partials * recip
        int idx = p*256 + tid;
        int row = idx >> 4, f4 = idx & 15;
        size_t off = (size_t)(mbase + row)*DD + f4*4;
        float4 a0 = *(const float4*)(g_headp + off);
        float4 a1 = *(const float4*)(g_headp + (size_t)RR*DD + off);
        float4 a2 = *(const float4*)(g_headp + (size_t)2*RR*DD + off);
        float4 a3 = *(const float4*)(g_headp + (size_t)3*RR*DD + off);
        float rc = s_recip[row];
        float4 h4 = make_float4(((a0.x+a1.x)+(a2.x+a3.x))*rc, ((a0.y+a1.y)+(a2.y+a3.y))*rc,
                                ((a0.z+a1.z)+(a2.z+a3.z))*rc, ((a0.w+a1.w)+(a2.w+a3.w))*rc);
        unsigned h0, l0, h1, l1;
        split2(h4.x, h4.y, h0, l0); split2(h4.z, h4.w, h1, l1);
        *(uint2*)&Hh[row*AP + f4*2] = make_uint2(h0, h1);
        *(uint2*)&Hl[row*AP + f4*2] = make_uint2(l0, l1);
    }
#pragma unroll
    for (int p = 0; p < 4; p++) {              // Weff^T stage
        int idx = p*256 + tid;
        int n = idx >> 3, k4 = (idx & 7) * 4;
        *(uint4*)&Wh[n*AP + k4] = *(const uint4*)&g_wefft_h[(nbase + n)*32 + k4];
        *(uint4*)&Wl[n*AP + k4] = *(const uint4*)&g_wefft_l[(nbase + n)*32 + k4];
    }
    __syncthreads();

    float acc[8][4] = {};
#pragma unroll
    for (int c = 0; c < 4; c++) {
        const int kc = c*8;
        unsigned ah[4], al[4];
        int r = wy*16 + g;
        ah[0] = Hh[ r     *AP + kc + t    ];
        ah[1] = Hh[(r + 8)*AP + kc + t    ];
        ah[2] = Hh[ r     *AP + kc + t + 4];
        ah[3] = Hh[(r + 8)*AP + kc + t + 4];
        al[0] = Hl[ r     *AP + kc + t    ];
        al[1] = Hl[(r + 8)*AP + kc + t    ];
        al[2] = Hl[ r     *AP + kc + t + 4];
        al[3] = Hl[(r + 8)*AP + kc + t + 4];
#pragma unroll
        for (int nt = 0; nt < 8; nt++) {
            int n = wx*64 + nt*8 + g;
            unsigned bh[2], bl[2];
            bh[0] = Wh[n*AP + kc + t];     bh[1] = Wh[n*AP + kc + t + 4];
            bl[0] = Wl[n*AP + kc + t];     bl[1] = Wl[n*AP + kc + t + 4];
            mma3(acc[nt], ah, al, bh, bl);
        }
    }

    int r0 = mbase + wy*16 + g, r1 = r0 + 8;
#pragma unroll
    for (int nt = 0; nt < 8; nt++) {
        int col = nbase + wx*64 + nt*8 + 2*t;
        float b0 = bout[col], b1 = bout[col+1];
        *(float2*)(out + (size_t)r0*HID + col) = make_float2(acc[nt][0]+b0, acc[nt][1]+b1);
        *(float2*)(out + (size_t)r1*HID + col) = make_float2(acc[nt][2]+b0, acc[nt][3]+b1);
    }
}

// ---------------------------------------------------------------------------
extern "C" void kernel_launch(void* const* d_in, const int* in_sizes, int n_in,
                              void* d_out, int out_size) {
    (void)in_sizes; (void)n_in; (void)out_size;
    const float* query = (const float*)d_in[0];
    const float* key   = (const float*)d_in[1];
    const float* value = (const float*)d_in[2];
    // d_in[3] mask: adding -1e-32 is a numeric no-op in fp32 -> skipped
    const float* Wq   = (const float*)d_in[4];
    const float* bq   = (const float*)d_in[5];
    const float* Wk   = (const float*)d_in[6];
    const float* bk   = (const float*)d_in[7];
    const float* Wv   = (const float*)d_in[8];
    const float* bv   = (const float*)d_in[9];
    const float* Wout = (const float*)d_in[10];
    const float* bout = (const float*)d_in[11];
    // d_in[12] seq_mask == 0 -> no causal mask
    float* out = (float*)d_out;

    const int proj_smem   = (2*128*AP + 2*64*AP) * 4;    // 55296 B
    const int scores_smem = (2*128*AP + 2*64*AP) * 4;    // 55296 B
    const int pv_smem     = (2*32*PP + 2*64*VP) * 4;     // 54272 B
    const int out_smem    = (2*64*AP + 2*128*AP) * 4;    // 55296 B
    cudaFuncSetAttribute(proj_mma,   cudaFuncAttributeMaxDynamicSharedMemorySize, proj_smem);
    cudaFuncSetAttribute(scores_mma, cudaFuncAttributeMaxDynamicSharedMemorySize, scores_smem);
    cudaFuncSetAttribute(pv_mma,     cudaFuncAttributeMaxDynamicSharedMemorySize, pv_smem);
    cudaFuncSetAttribute(out_mma,    cudaFuncAttributeMaxDynamicSharedMemorySize, out_smem);

    wqkvt_prep<<<dim3(128, 3), 256>>>(Wq, Wk, Wv);
    wefft_prep<<<dim3(4, 32), 256>>>(Wout);
    proj_mma<<<dim3(64, 3), 256, proj_smem>>>(query, key, value, bq, bk, bv);
    scores_mma<<<dim3(NJT, 16, 4), 256, scores_smem>>>();
    stats_finalize<<<RR/256, 256>>>();
    pv_mma<<<dim3(64, 4, NSPLIT), 256, pv_smem>>>();
    out_mma<<<dim3(128, 8), 256, out_smem>>>(bout, out);
}